// round 14
// baseline (speedup 1.0000x reference)
#include <cuda_runtime.h>
#include <cuda_fp16.h>
#include <cstdint>

// Problem constants (fixed by setup_inputs)
#define B_SZ   32
#define D_IN   32
#define D_OUT  32
#define N_NODE 2000
#define H_DIM  64
#define E_DIM  16
#define NPER   24
#define ESTRIDE 160          // padded ELL stride (row nnz ~Binom(2000,.05): mean 100, max ~135)
#define NCHUNK 63            // ceil(2000/32)
#define MAXB   4             // batches handled per warp-pass in the fused kernel
#define PASSES 8             // MAXB*PASSES = 32 covers any period multiplicity

// fused-preamble block ranges
#define PRE_ENV_BLKS (N_NODE + 1)
#define PRE_CSR_BASE PRE_ENV_BLKS
#define PRE_SUP_BASE (PRE_CSR_BASE + N_NODE)
#define PRE_BLKS     (PRE_SUP_BASE + B_SZ * N_NODE / 64)

// ---------------- f32x2 packed-math helpers (Blackwell FFMA2) -----------------
__device__ __forceinline__ unsigned long long pk_dup(float x) {
    unsigned long long r;
    asm("mov.b64 %0, {%1, %1};" : "=l"(r) : "f"(x));
    return r;
}
__device__ __forceinline__ unsigned long long pk2(float lo, float hi) {
    unsigned long long r;
    asm("mov.b64 %0, {%1, %2};" : "=l"(r) : "f"(lo), "f"(hi));
    return r;
}
__device__ __forceinline__ void unpk2(unsigned long long v, float& lo, float& hi) {
    asm("mov.b64 {%0, %1}, %2;" : "=f"(lo), "=f"(hi) : "l"(v));
}
__device__ __forceinline__ unsigned long long fma2(unsigned long long a,
                                                   unsigned long long b,
                                                   unsigned long long c) {
    unsigned long long d;
    asm("fma.rn.f32x2 %0, %1, %2, %3;" : "=l"(d) : "l"(a), "l"(b), "l"(c));
    return d;
}
__device__ __forceinline__ unsigned long long f2u(float2 f) {
    unsigned long long r;
    asm("mov.b64 %0, {%1, %2};" : "=l"(r) : "f"(f.x), "f"(f.y));
    return r;
}

// ---------------- static device scratch (no allocations allowed) -------------
__device__ float  g_env[N_NODE * H_DIM];                        // 0.5 MB
__device__ __half g_T[NPER * N_NODE * H_DIM];                   // 6.1 MB fp16, 128B rows
__device__ int    g_ecol[N_NODE * ESTRIDE];                     // 1.3 MB (col-sorted, 0-padded)
__device__ float  g_ew[N_NODE * ESTRIDE];                       // 1.3 MB
__device__ int    g_elen[N_NODE];
__device__ __half g_sup[B_SZ * N_NODE * D_OUT];                 // 4.1 MB fp16, 64B rows
__device__ float  g_resid[B_SZ * N_NODE * D_OUT];               // 8.2 MB
__device__ int    g_pbcnt[NPER];                                // batches per period
__device__ int    g_pblist[NPER * B_SZ];                        // batch lists per period
__device__ int    g_used[NPER];

// ---------------- K1 (fused preamble): env+period | csr | supres ---------------
union PreSmem {
    struct { unsigned masks[NCHUNK]; int offs[NCHUNK]; } csr;
    unsigned long long xd[64 * 32];              // 16 KB supres x-stage
};

__global__ void __launch_bounds__(256) k_pre(const float* __restrict__ envf,
                                             const float* __restrict__ Wenv,
                                             const float* __restrict__ benv,
                                             const int* __restrict__ cyc,
                                             const float* __restrict__ adj,
                                             const float* __restrict__ inf,
                                             const float* __restrict__ weight,
                                             const float* __restrict__ W_res,
                                             const float* __restrict__ b_res) {
    __shared__ PreSmem sm;
    int blk = blockIdx.x;

    if (blk < PRE_ENV_BLKS) {
        if (blk == N_NODE) {                     // period block
            int t = threadIdx.x;
            if (t < NPER) { g_used[t] = 0; g_pbcnt[t] = 0; }
            __syncthreads();
            if (t == 0) {                        // serial: deterministic lists
                for (int b = 0; b < B_SZ; b++) {
                    int p = cyc[b] % NPER;
                    g_used[p] = 1;
                    g_pblist[p * B_SZ + g_pbcnt[p]] = b;
                    g_pbcnt[p]++;
                }
            }
            return;
        }
        int h = threadIdx.x;
        if (h >= H_DIM) return;
        int n = blk;
        const float* er = envf + n * E_DIM;
        float acc = benv[h];
#pragma unroll
        for (int e = 0; e < E_DIM; e++)
            acc = fmaf(er[e], Wenv[e * H_DIM + h], acc);
        g_env[n * H_DIM + h] = fmaxf(acc, 0.0f);
        return;
    }

    if (blk < PRE_SUP_BASE) {
        // ---- csr: padded ELL build, single adj pass ----
        int row = blk - PRE_CSR_BASE;
        int w = threadIdx.x >> 5;
        int lane = threadIdx.x & 31;
        const float* r = adj + (size_t)row * N_NODE;

        float vr[8];
        int it = 0;
        for (int c = w; c < NCHUNK; c += 8, it++) {
            int col = c * 32 + lane;
            float v = (col < N_NODE) ? r[col] : 0.0f;
            vr[it] = v;
            unsigned m = __ballot_sync(0xffffffffu, v != 0.0f);
            if (lane == 0) sm.csr.masks[c] = m;
        }
        __syncthreads();
        if (threadIdx.x == 0) {
            int a = 0;
            for (int c = 0; c < NCHUNK; c++) { sm.csr.offs[c] = a; a += __popc(sm.csr.masks[c]); }
            g_elen[row] = a;
        }
        __syncthreads();
        it = 0;
        for (int c = w; c < NCHUNK; c += 8, it++) {
            int col = c * 32 + lane;
            float v = vr[it];
            if (v != 0.0f) {
                int pos = sm.csr.offs[c] + __popc(sm.csr.masks[c] & ((1u << lane) - 1u));
                if (pos < ESTRIDE) {
                    g_ecol[row * ESTRIDE + pos] = col;
                    g_ew[row * ESTRIDE + pos] = v;
                }
            }
        }
        int len = g_elen[row];
        for (int k = len + threadIdx.x; k < ESTRIDE; k += blockDim.x) {
            g_ecol[row * ESTRIDE + k] = 0;       // pad: col 0, weight 0 -> exact zeros
            g_ew[row * ESTRIDE + k] = 0.0f;
        }
        return;
    }

    // ---- supres: support(fp16, batch-major 64B rows) + resid via f32x2 FMA ----
    {
        int t = threadIdx.x;
        int base = (blk - PRE_SUP_BASE) * 64;

        const float4* xin = (const float4*)(inf + ((size_t)base << 5));
#pragma unroll
        for (int r = 0; r < 2; r++) {
            int fi = t + r * 256;
            float4 v = xin[fi];
            unsigned long long* dst = &sm.xd[fi * 4];
            dst[0] = pk_dup(v.x);
            dst[1] = pk_dup(v.y);
            dst[2] = pk_dup(v.z);
            dst[3] = pk_dup(v.w);
        }
        __syncthreads();

        int wid = t >> 5;
        int lane = t & 31;
        unsigned long long wq[D_IN];
#pragma unroll
        for (int d = 0; d < D_IN; d++)
            wq[d] = pk2(weight[d * D_OUT + lane], W_res[d * D_OUT + lane]);
        unsigned long long acc0 = pk2(0.0f, b_res[lane]);

#pragma unroll
        for (int i = 0; i < 8; i++) {
            int node = wid * 8 + i;
            const ulonglong2* xp = (const ulonglong2*)&sm.xd[node * 32];
            unsigned long long acc = acc0;
#pragma unroll
            for (int d2 = 0; d2 < 16; d2++) {
                ulonglong2 p = xp[d2];
                acc = fma2(p.x, wq[2 * d2], acc);
                acc = fma2(p.y, wq[2 * d2 + 1], acc);
            }
            float as, ar;
            unpk2(acc, as, ar);
            size_t o = (((size_t)(base + node)) << 5) + lane;
            g_sup[o] = __float2half(as);
            g_resid[o] = fmaxf(ar, 0.0f);
        }
    }
}

// ---------------- K2: T = tgt + env (fp16, row-contig), used periods only -----
__global__ void k_T(const float* __restrict__ tgt) {
    int i = blockIdx.x * blockDim.x + threadIdx.x;
    const int TOT = NPER * N_NODE * H_DIM;
    if (i >= TOT) return;
    int p = (i >> 6) / N_NODE;
    if (!g_used[p]) return;
    g_T[i] = __float2half(tgt[i] + g_env[i % (N_NODE * H_DIM)]);
}

// ---------------- K3 (FUSED): A-chunk in registers -> SpMM for p's batches -----
// warp = (pass, p, n). Aval phase: 8 lanes/edge, 16 edges/chunk, MLP4 (R7 code).
// Out phase: redistribute a-values to lanes 0-15, then R7 k_out inner body for
// up to MAXB batches of period p; per-batch f32x2 accumulators live in regs.
// g_aval never exists in memory.
__global__ void __launch_bounds__(256) k_fused(const float* __restrict__ src,
                                               const float* __restrict__ bias,
                                               float* __restrict__ out) {
    int gw = (blockIdx.x * blockDim.x + threadIdx.x) >> 5;
    int lane = threadIdx.x & 31;
    int pass = gw / (NPER * N_NODE);
    int pn = gw - pass * (NPER * N_NODE);
    int p = pn / N_NODE;
    int n = pn - p * N_NODE;
    int cnt = g_pbcnt[p];                        // 0 for unused periods
    int bi0 = pass * MAXB;
    if (bi0 >= cnt) return;
    int nb = min(MAXB, cnt - bi0);
    int bs[MAXB];
#pragma unroll
    for (int j = 0; j < MAXB; j++)
        bs[j] = g_pblist[p * B_SZ + ((bi0 + j < cnt) ? (bi0 + j) : bi0)];

    int sub8 = lane >> 3;        // aval: edge subgroup 0..3
    int q8 = lane & 7;           // aval: dim-slice [8q8, 8q8+8)
    int sub4 = lane >> 2;        // out: edge subgroup 0..7
    int q4 = lane & 3;           // out: m-slice [8q4, 8q4+8)

    // S slice (src + env), read once per row
    const float* srow = src + ((size_t)pn << 6) + q8 * 8;
    const float* erow = g_env + ((size_t)n << 6) + q8 * 8;
    float4 a0 = *(const float4*)srow;
    float4 a1 = *(const float4*)(srow + 4);
    float4 e0 = *(const float4*)erow;
    float4 e1 = *(const float4*)(erow + 4);
    float4 s0 = make_float4(a0.x + e0.x, a0.y + e0.y, a0.z + e0.z, a0.w + e0.w);
    float4 s1 = make_float4(a1.x + e1.x, a1.y + e1.y, a1.z + e1.z, a1.w + e1.w);

    const __half* Tp = g_T + ((size_t)p * N_NODE << 6);
    const int eb = n * ESTRIDE;
    int padlen = (g_elen[n] + 15) & ~15;

    unsigned long long Acc[MAXB][4];
#pragma unroll
    for (int j = 0; j < MAXB; j++) {
        Acc[j][0] = 0; Acc[j][1] = 0; Acc[j][2] = 0; Acc[j][3] = 0;
    }

    for (int k0 = 0; k0 < padlen; k0 += 16) {
        // ---- aval phase (identical arithmetic to R7 k_aval) ----
        int cc = 0; float ww = 0.0f;
        if (lane < 16) { cc = g_ecol[eb + k0 + lane]; ww = g_ew[eb + k0 + lane]; }
        int c[4];
#pragma unroll
        for (int i = 0; i < 4; i++)
            c[i] = __shfl_sync(0xffffffffu, cc, sub8 + 4 * i);
        uint4 t[4];
#pragma unroll
        for (int i = 0; i < 4; i++)                  // 4 independent T gathers
            t[i] = *(const uint4*)(Tp + ((size_t)c[i] << 6) + q8 * 8);

        float d[4];
#pragma unroll
        for (int i = 0; i < 4; i++) {
            float2 f0 = __half22float2(*(const __half2*)&t[i].x);
            float2 f1 = __half22float2(*(const __half2*)&t[i].y);
            float2 f2 = __half22float2(*(const __half2*)&t[i].z);
            float2 f3 = __half22float2(*(const __half2*)&t[i].w);
            float dd = s0.x * f0.x;
            dd = fmaf(s0.y, f0.y, dd);
            dd = fmaf(s0.z, f1.x, dd);
            dd = fmaf(s0.w, f1.y, dd);
            dd = fmaf(s1.x, f2.x, dd);
            dd = fmaf(s1.y, f2.y, dd);
            dd = fmaf(s1.z, f3.x, dd);
            dd = fmaf(s1.w, f3.y, dd);
            d[i] = dd;
        }
#pragma unroll
        for (int o = 1; o <= 4; o <<= 1) {
#pragma unroll
            for (int i = 0; i < 4; i++)
                d[i] += __shfl_xor_sync(0xffffffffu, d[i], o);
        }

        // ---- redistribute: lane l<16 takes a-value of edge k0+l (R10 trick) ----
        int srcl = (lane & 3) << 3;
        float v0 = __shfl_sync(0xffffffffu, d[0], srcl);
        float v1 = __shfl_sync(0xffffffffu, d[1], srcl);
        float v2 = __shfl_sync(0xffffffffu, d[2], srcl);
        float v3 = __shfl_sync(0xffffffffu, d[3], srcl);
        int iq = lane >> 2;
        float val = (iq == 0) ? v0 : (iq == 1) ? v1 : (iq == 2) ? v2 : v3;
        float aa = fmaxf(val, 0.0f) * ww;            // pads: ww=0 -> exact 0

        // ---- out phase (identical accumulation order to R7 k_out) ----
        int   ce0 = __shfl_sync(0xffffffffu, cc, sub4);
        float ae0 = __shfl_sync(0xffffffffu, aa, sub4);
        int   ce1 = __shfl_sync(0xffffffffu, cc, 8 + sub4);
        float ae1 = __shfl_sync(0xffffffffu, aa, 8 + sub4);
        unsigned long long ap0 = pk_dup(ae0);
        unsigned long long ap1 = pk_dup(ae1);
#pragma unroll
        for (int j = 0; j < MAXB; j++) {
            if (j < nb) {
                const __half* Sb = g_sup + ((size_t)bs[j] * N_NODE << 5);
                uint4 u0 = *(const uint4*)(Sb + ((size_t)ce0 << 5) + q4 * 8);
                uint4 u1 = *(const uint4*)(Sb + ((size_t)ce1 << 5) + q4 * 8);
                Acc[j][0] = fma2(ap0, f2u(__half22float2(*(const __half2*)&u0.x)), Acc[j][0]);
                Acc[j][1] = fma2(ap0, f2u(__half22float2(*(const __half2*)&u0.y)), Acc[j][1]);
                Acc[j][2] = fma2(ap0, f2u(__half22float2(*(const __half2*)&u0.z)), Acc[j][2]);
                Acc[j][3] = fma2(ap0, f2u(__half22float2(*(const __half2*)&u0.w)), Acc[j][3]);
                Acc[j][0] = fma2(ap1, f2u(__half22float2(*(const __half2*)&u1.x)), Acc[j][0]);
                Acc[j][1] = fma2(ap1, f2u(__half22float2(*(const __half2*)&u1.y)), Acc[j][1]);
                Acc[j][2] = fma2(ap1, f2u(__half22float2(*(const __half2*)&u1.z)), Acc[j][2]);
                Acc[j][3] = fma2(ap1, f2u(__half22float2(*(const __half2*)&u1.w)), Acc[j][3]);
            }
        }
    }

    // ---- per-batch reduction over the 8 edge subgroups + epilogue ----
#pragma unroll
    for (int j = 0; j < MAXB; j++) {
        if (j < nb) {
            float acc[8];
            unpk2(Acc[j][0], acc[0], acc[1]);
            unpk2(Acc[j][1], acc[2], acc[3]);
            unpk2(Acc[j][2], acc[4], acc[5]);
            unpk2(Acc[j][3], acc[6], acc[7]);
#pragma unroll
            for (int o = 4; o < 32; o <<= 1) {
#pragma unroll
                for (int m = 0; m < 8; m++)
                    acc[m] += __shfl_xor_sync(0xffffffffu, acc[m], o);
            }
            if (lane < 4) {      // lane = q4, sub4 = 0: holds m-slice [8q4, 8q4+8)
                int o = ((bs[j] * N_NODE + n) << 5) + q4 * 8;
                float4 r0 = *(const float4*)(g_resid + o);
                float4 r1 = *(const float4*)(g_resid + o + 4);
                float4 b0 = *(const float4*)(bias + q4 * 8);
                float4 b1 = *(const float4*)(bias + q4 * 8 + 4);
                float4 y0, y1;
                y0.x = fmaxf(acc[0] + b0.x + r0.x, 0.0f);
                y0.y = fmaxf(acc[1] + b0.y + r0.y, 0.0f);
                y0.z = fmaxf(acc[2] + b0.z + r0.z, 0.0f);
                y0.w = fmaxf(acc[3] + b0.w + r0.w, 0.0f);
                y1.x = fmaxf(acc[4] + b1.x + r1.x, 0.0f);
                y1.y = fmaxf(acc[5] + b1.y + r1.y, 0.0f);
                y1.z = fmaxf(acc[6] + b1.z + r1.z, 0.0f);
                y1.w = fmaxf(acc[7] + b1.w + r1.w, 0.0f);
                *(float4*)(out + o) = y0;
                *(float4*)(out + o + 4) = y1;
            }
        }
    }
}

// ------------------------------- launcher -------------------------------------
extern "C" void kernel_launch(void* const* d_in, const int* in_sizes, int n_in,
                              void* d_out, int out_size) {
    const float* inf    = (const float*)d_in[0];
    const int*   cyc    = (const int*)  d_in[1];
    const float* adj    = (const float*)d_in[2];
    const float* envf   = (const float*)d_in[3];
    const float* W_env  = (const float*)d_in[4];
    const float* b_env  = (const float*)d_in[5];
    const float* src    = (const float*)d_in[6];
    const float* tgt    = (const float*)d_in[7];
    const float* weight = (const float*)d_in[8];
    const float* bias   = (const float*)d_in[9];
    const float* W_res  = (const float*)d_in[10];
    const float* b_res  = (const float*)d_in[11];
    float* out = (float*)d_out;

    k_pre   <<<PRE_BLKS, 256>>>(envf, W_env, b_env, cyc, adj, inf, weight, W_res, b_res);
    k_T     <<<(NPER * N_NODE * H_DIM + 255) / 256, 256>>>(tgt);
    k_fused <<<(PASSES * NPER * N_NODE) / 8, 256>>>(src, bias, out);
}

// round 15
// speedup vs baseline: 1.2953x; 1.2953x over previous
#include <cuda_runtime.h>
#include <cuda_fp16.h>
#include <cstdint>

// Problem constants (fixed by setup_inputs)
#define B_SZ   32
#define D_IN   32
#define D_OUT  32
#define N_NODE 2000
#define H_DIM  64
#define E_DIM  16
#define NPER   24
#define ESTRIDE 160          // padded ELL stride (row nnz ~Binom(2000,.05): mean 100, max ~135)
#define NCHUNK 63            // ceil(2000/32)

// ---------------- f32x2 packed-math helpers (Blackwell FFMA2) -----------------
__device__ __forceinline__ unsigned long long pk_dup(float x) {
    unsigned long long r;
    asm("mov.b64 %0, {%1, %1};" : "=l"(r) : "f"(x));
    return r;
}
__device__ __forceinline__ unsigned long long pk2(float lo, float hi) {
    unsigned long long r;
    asm("mov.b64 %0, {%1, %2};" : "=l"(r) : "f"(lo), "f"(hi));
    return r;
}
__device__ __forceinline__ void unpk2(unsigned long long v, float& lo, float& hi) {
    asm("mov.b64 {%0, %1}, %2;" : "=f"(lo), "=f"(hi) : "l"(v));
}
__device__ __forceinline__ unsigned long long fma2(unsigned long long a,
                                                   unsigned long long b,
                                                   unsigned long long c) {
    unsigned long long d;
    asm("fma.rn.f32x2 %0, %1, %2, %3;" : "=l"(d) : "l"(a), "l"(b), "l"(c));
    return d;
}
__device__ __forceinline__ unsigned long long f2u(float2 f) {
    unsigned long long r;
    asm("mov.b64 %0, {%1, %2};" : "=l"(r) : "f"(f.x), "f"(f.y));
    return r;
}

// ---------------- static device scratch (no allocations allowed) -------------
__device__ float  g_env[N_NODE * H_DIM];                        // 0.5 MB
__device__ __half g_T[NPER * N_NODE * H_DIM];                   // 6.1 MB fp16, 128B rows
__device__ int    g_ecol[N_NODE * ESTRIDE];                     // 1.3 MB (col-sorted, 0-padded)
__device__ float  g_ew[N_NODE * ESTRIDE];                       // 1.3 MB
__device__ int    g_elen[N_NODE];
__device__ float  g_aval[(size_t)NPER * N_NODE * ESTRIDE];      // 30.7 MB
__device__ __half g_sup[B_SZ * N_NODE * D_OUT];                 // 4.1 MB fp16, 64B rows
__device__ float  g_resid[B_SZ * N_NODE * D_OUT];               // 8.2 MB
__device__ int    g_used[NPER];
__device__ int    g_period[B_SZ];

// ---------------- K1: env = relu(env@W+b)  +  per-batch periods (fused) -------
__global__ void k_envper(const float* __restrict__ envf,
                         const float* __restrict__ W,
                         const float* __restrict__ b,
                         const int* __restrict__ cyc) {
    if (blockIdx.x == N_NODE) {
        int t = threadIdx.x;
        if (t < NPER) g_used[t] = 0;
        __syncthreads();
        if (t < B_SZ) {
            int p = cyc[t] % NPER;
            g_period[t] = p;
            g_used[p] = 1;                   // racy same-value stores: deterministic
        }
        return;
    }
    int n = blockIdx.x;
    int h = threadIdx.x;                     // 64 threads
    const float* er = envf + n * E_DIM;
    float acc = b[h];
#pragma unroll
    for (int e = 0; e < E_DIM; e++)
        acc = fmaf(er[e], W[e * H_DIM + h], acc);
    g_env[n * H_DIM + h] = fmaxf(acc, 0.0f);
}

// ---------------- K2: padded ELL build, single adj pass (values reg-cached) ---
__global__ void k_csr(const float* __restrict__ adj) {
    __shared__ unsigned masks[NCHUNK];
    __shared__ int offs[NCHUNK];
    int row = blockIdx.x;
    int w = threadIdx.x >> 5;                // 8 warps
    int lane = threadIdx.x & 31;
    const float* r = adj + (size_t)row * N_NODE;

    float vr[8];
    int it = 0;
    for (int c = w; c < NCHUNK; c += 8, it++) {
        int col = c * 32 + lane;
        float v = (col < N_NODE) ? r[col] : 0.0f;
        vr[it] = v;
        unsigned m = __ballot_sync(0xffffffffu, v != 0.0f);
        if (lane == 0) masks[c] = m;
    }
    __syncthreads();
    if (threadIdx.x == 0) {
        int a = 0;
        for (int c = 0; c < NCHUNK; c++) { offs[c] = a; a += __popc(masks[c]); }
        g_elen[row] = a;
    }
    __syncthreads();
    it = 0;
    for (int c = w; c < NCHUNK; c += 8, it++) {
        int col = c * 32 + lane;
        float v = vr[it];
        if (v != 0.0f) {
            int pos = offs[c] + __popc(masks[c] & ((1u << lane) - 1u));
            if (pos < ESTRIDE) {
                g_ecol[row * ESTRIDE + pos] = col;
                g_ew[row * ESTRIDE + pos] = v;
            }
        }
    }
    int len = g_elen[row];
    for (int k = len + threadIdx.x; k < ESTRIDE; k += blockDim.x) {
        g_ecol[row * ESTRIDE + k] = 0;       // pad: col 0, weight 0 -> exact zeros
        g_ew[row * ESTRIDE + k] = 0.0f;
    }
}

// ---------------- K3: T = tgt + env (fp16, row-contig), used periods only -----
__global__ void k_T(const float* __restrict__ tgt) {
    int i = blockIdx.x * blockDim.x + threadIdx.x;
    const int TOT = NPER * N_NODE * H_DIM;
    if (i >= TOT) return;
    int p = (i >> 6) / N_NODE;
    if (!g_used[p]) return;
    g_T[i] = __float2half(tgt[i] + g_env[i % (N_NODE * H_DIM)]);
}

// ---------------- K4: support(fp16) + resid via packed f32x2 FMA --------------
// block = 64 nodes (8 per warp) — R5 config (measured 15.1-15.4us)
__global__ void __launch_bounds__(256) k_supres(const float* __restrict__ inf,
                         const float* __restrict__ weight,
                         const float* __restrict__ W_res,
                         const float* __restrict__ b_res) {
    __shared__ unsigned long long xd[64 * 32];   // 16 KB: xd[node*32+d] = (x,x)
    int t = threadIdx.x;
    int base = blockIdx.x * 64;

    const float4* xin = (const float4*)(inf + ((size_t)base << 5));
#pragma unroll
    for (int r = 0; r < 2; r++) {
        int fi = t + r * 256;
        float4 v = xin[fi];
        unsigned long long* dst = &xd[fi * 4];
        dst[0] = pk_dup(v.x);
        dst[1] = pk_dup(v.y);
        dst[2] = pk_dup(v.z);
        dst[3] = pk_dup(v.w);
    }
    __syncthreads();

    int wid = t >> 5;
    int lane = t & 31;
    unsigned long long wq[D_IN];
#pragma unroll
    for (int d = 0; d < D_IN; d++)
        wq[d] = pk2(weight[d * D_OUT + lane], W_res[d * D_OUT + lane]);
    unsigned long long acc0 = pk2(0.0f, b_res[lane]);

#pragma unroll
    for (int i = 0; i < 8; i++) {
        int node = wid * 8 + i;
        const ulonglong2* xp = (const ulonglong2*)&xd[node * 32];
        unsigned long long acc = acc0;
#pragma unroll
        for (int d2 = 0; d2 < 16; d2++) {
            ulonglong2 p = xp[d2];               // LDS.128, broadcast
            acc = fma2(p.x, wq[2 * d2], acc);
            acc = fma2(p.y, wq[2 * d2 + 1], acc);
        }
        float as, ar;
        unpk2(acc, as, ar);
        size_t o = (((size_t)(base + node)) << 5) + lane;
        g_sup[o] = __float2half(as);
        g_resid[o] = fmaxf(ar, 0.0f);
    }
}

// ---------------- K5: A_val = relu((src+env)[row]·T[col]) * w ------------------
// warp per (p,row); 8 lanes/edge; 16 edges per iter, 4 gathers in flight.
// launch_bounds(256,6): force >=6 blocks/SM (48 warps) for latency hiding.
__global__ void __launch_bounds__(256, 6) k_aval(const float* __restrict__ src) {
    int gw = (blockIdx.x * blockDim.x + threadIdx.x) >> 5;
    int lane = threadIdx.x & 31;
    int p = gw / N_NODE;
    if (p >= NPER) return;
    if (!g_used[p]) return;
    int n = gw - p * N_NODE;
    int sub = lane >> 3;         // 0..3
    int q = lane & 7;            // dim-slice: halves [8q, 8q+8)

    const float* srow = src + ((size_t)(p * N_NODE + n) << 6) + q * 8;
    const float* erow = g_env + ((size_t)n << 6) + q * 8;
    float4 a0 = *(const float4*)srow;
    float4 a1 = *(const float4*)(srow + 4);
    float4 e0 = *(const float4*)erow;
    float4 e1 = *(const float4*)(erow + 4);
    float4 s0 = make_float4(a0.x + e0.x, a0.y + e0.y, a0.z + e0.z, a0.w + e0.w);
    float4 s1 = make_float4(a1.x + e1.x, a1.y + e1.y, a1.z + e1.z, a1.w + e1.w);

    const __half* Tp = g_T + ((size_t)p * N_NODE << 6);
    const int eb = n * ESTRIDE;
    float* outp = g_aval + (size_t)p * (N_NODE * ESTRIDE) + eb;
    int padlen = (g_elen[n] + 15) & ~15;

    for (int k0 = 0; k0 < padlen; k0 += 16) {
        int cc = 0; float ww = 0.0f;
        if (lane < 16) { cc = g_ecol[eb + k0 + lane]; ww = g_ew[eb + k0 + lane]; }
        int c[4]; float wv[4];
#pragma unroll
        for (int i = 0; i < 4; i++) {
            c[i]  = __shfl_sync(0xffffffffu, cc, sub + 4 * i);
            wv[i] = __shfl_sync(0xffffffffu, ww, sub + 4 * i);
        }
        uint4 t[4];
#pragma unroll
        for (int i = 0; i < 4; i++)                  // 4 independent gathers
            t[i] = *(const uint4*)(Tp + ((size_t)c[i] << 6) + q * 8);

        float d[4];
#pragma unroll
        for (int i = 0; i < 4; i++) {
            float2 f0 = __half22float2(*(const __half2*)&t[i].x);
            float2 f1 = __half22float2(*(const __half2*)&t[i].y);
            float2 f2 = __half22float2(*(const __half2*)&t[i].z);
            float2 f3 = __half22float2(*(const __half2*)&t[i].w);
            float dd = s0.x * f0.x;
            dd = fmaf(s0.y, f0.y, dd);
            dd = fmaf(s0.z, f1.x, dd);
            dd = fmaf(s0.w, f1.y, dd);
            dd = fmaf(s1.x, f2.x, dd);
            dd = fmaf(s1.y, f2.y, dd);
            dd = fmaf(s1.z, f3.x, dd);
            dd = fmaf(s1.w, f3.y, dd);
            d[i] = dd;
        }
#pragma unroll
        for (int o = 1; o <= 4; o <<= 1) {
#pragma unroll
            for (int i = 0; i < 4; i++)
                d[i] += __shfl_xor_sync(0xffffffffu, d[i], o);
        }
        if (q == 0) {
#pragma unroll
            for (int i = 0; i < 4; i++)
                outp[k0 + sub + 4 * i] = fmaxf(d[i], 0.0f) * wv[i];
        }
    }
}

// ---------------- K6: out = relu(A[p_b]@support + bias + resid) ----------------
// warp per (b,n); 4 lanes/edge; 32 edges per iter, 4 gathers in flight.
// launch_bounds(256,5): force >=5 blocks/SM (40 warps).
__global__ void __launch_bounds__(256, 5) k_out(const float* __restrict__ bias,
                                                float* __restrict__ out) {
    int gw = (blockIdx.x * blockDim.x + threadIdx.x) >> 5;   // b*N + n
    int lane = threadIdx.x & 31;
    if (gw >= B_SZ * N_NODE) return;
    int b = gw / N_NODE;
    int n = gw - b * N_NODE;
    int p = g_period[b];
    int sub = lane >> 2;         // 0..7
    int q = lane & 3;            // m-slice: m in [8q, 8q+8)

    const float* Ap = g_aval + (size_t)p * (N_NODE * ESTRIDE) + n * ESTRIDE;
    const __half* Sb = g_sup + ((size_t)b * N_NODE << 5);
    const int eb = n * ESTRIDE;
    int padlen = (g_elen[n] + 31) & ~31;

    unsigned long long A0 = 0, A1 = 0, A2 = 0, A3 = 0;   // 4x packed f32x2

    for (int k0 = 0; k0 < padlen; k0 += 32) {
        int cc = g_ecol[eb + k0 + lane];                 // all 32 lanes, coalesced
        float aa = Ap[k0 + lane];
        int c[4]; float a[4];
#pragma unroll
        for (int i = 0; i < 4; i++) {
            c[i] = __shfl_sync(0xffffffffu, cc, sub + 8 * i);
            a[i] = __shfl_sync(0xffffffffu, aa, sub + 8 * i);
        }
        uint4 t[4];
#pragma unroll
        for (int i = 0; i < 4; i++)                      // 4 independent gathers
            t[i] = *(const uint4*)(Sb + ((size_t)c[i] << 5) + q * 8);
#pragma unroll
        for (int i = 0; i < 4; i++) {
            unsigned long long ap = pk_dup(a[i]);
            A0 = fma2(ap, f2u(__half22float2(*(const __half2*)&t[i].x)), A0);
            A1 = fma2(ap, f2u(__half22float2(*(const __half2*)&t[i].y)), A1);
            A2 = fma2(ap, f2u(__half22float2(*(const __half2*)&t[i].z)), A2);
            A3 = fma2(ap, f2u(__half22float2(*(const __half2*)&t[i].w)), A3);
        }
    }

    float acc[8];
    unpk2(A0, acc[0], acc[1]);
    unpk2(A1, acc[2], acc[3]);
    unpk2(A2, acc[4], acc[5]);
    unpk2(A3, acc[6], acc[7]);

    // reduce over the 8 edge subgroups (lanes with equal q)
#pragma unroll
    for (int o = 4; o < 32; o <<= 1) {
#pragma unroll
        for (int j = 0; j < 8; j++)
            acc[j] += __shfl_xor_sync(0xffffffffu, acc[j], o);
    }

    if (lane < 4) {              // lane = q, sub = 0: holds m-slice [8q, 8q+8)
        int o = (gw << 5) + q * 8;
        float4 r0 = *(const float4*)(g_resid + o);
        float4 r1 = *(const float4*)(g_resid + o + 4);
        float4 b0 = *(const float4*)(bias + q * 8);
        float4 b1 = *(const float4*)(bias + q * 8 + 4);
        float4 y0, y1;
        y0.x = fmaxf(acc[0] + b0.x + r0.x, 0.0f);
        y0.y = fmaxf(acc[1] + b0.y + r0.y, 0.0f);
        y0.z = fmaxf(acc[2] + b0.z + r0.z, 0.0f);
        y0.w = fmaxf(acc[3] + b0.w + r0.w, 0.0f);
        y1.x = fmaxf(acc[4] + b1.x + r1.x, 0.0f);
        y1.y = fmaxf(acc[5] + b1.y + r1.y, 0.0f);
        y1.z = fmaxf(acc[6] + b1.z + r1.z, 0.0f);
        y1.w = fmaxf(acc[7] + b1.w + r1.w, 0.0f);
        *(float4*)(out + o) = y0;
        *(float4*)(out + o + 4) = y1;
    }
}

// ------------------------------- launcher -------------------------------------
extern "C" void kernel_launch(void* const* d_in, const int* in_sizes, int n_in,
                              void* d_out, int out_size) {
    const float* inf    = (const float*)d_in[0];
    const int*   cyc    = (const int*)  d_in[1];
    const float* adj    = (const float*)d_in[2];
    const float* envf   = (const float*)d_in[3];
    const float* W_env  = (const float*)d_in[4];
    const float* b_env  = (const float*)d_in[5];
    const float* src    = (const float*)d_in[6];
    const float* tgt    = (const float*)d_in[7];
    const float* weight = (const float*)d_in[8];
    const float* bias   = (const float*)d_in[9];
    const float* W_res  = (const float*)d_in[10];
    const float* b_res  = (const float*)d_in[11];
    float* out = (float*)d_out;

    k_envper<<<N_NODE + 1, H_DIM>>>(envf, W_env, b_env, cyc);
    k_csr   <<<N_NODE, 256>>>(adj);
    k_T     <<<(NPER * N_NODE * H_DIM + 255) / 256, 256>>>(tgt);
    k_supres<<<B_SZ * N_NODE / 64, 256>>>(inf, weight, W_res, b_res);
    k_aval  <<<(NPER * N_NODE + 7) / 8, 256>>>(src);
    k_out   <<<(B_SZ * N_NODE + 7) / 8, 256>>>(bias, out);
}